// round 9
// baseline (speedup 1.0000x reference)
#include <cuda_runtime.h>
#include <cuda_fp16.h>
#include <math.h>
#include <stdint.h>

#define H   16
#define BB  4
#define NN  512
#define DD  1024
#define DK  64
#define DR  128
#define BH  (BB*H)   // 64

// ---------------- scratch (static device globals; no allocation) ----------------
__device__ float g_qh  [BH*NN*DK];        // [bh][n][d]     8 MB
__device__ float g_khT [BH*DK*NN];        // [bh][d][n]     8 MB
__device__ float g_vh  [BH*NN*DK];        // [bh][n][d]     8 MB
__device__ float g_qtil[BH*NN*DR];        // [bh][n][e]    16 MB
__device__ float g_score[BH*NN*NN];       // [bh][m][n]    64 MB (score -> att in place)
__device__ float g_u   [BH*NN*DR];        // [bh][m][e]    16 MB
__device__ float g_av  [BH*NN*DK];        // [bh][m][d]     8 MB
__device__ float g_val [BB*NN*DD];        // [b][m][h*64+d] 8 MB
__device__ float g_WrkT[DK*DR];           // [d][e]

// ---------------- f16x2 split helpers (packed cvt: 1 SASS instr per 2 converts) ----
__device__ __forceinline__ uint32_t pack_split(float x, float y, uint32_t& lo2) {
    __half2 h2 = __float22half2_rn(make_float2(x, y));
    float2 back = __half22float2(h2);
    __half2 l2 = __float22half2_rn(make_float2(x - back.x, y - back.y));
    lo2 = *(uint32_t*)&l2;
    return *(uint32_t*)&h2;
}

__device__ __forceinline__ void mma_f16(float* d, const uint32_t* a, const uint32_t* b) {
    asm volatile(
        "mma.sync.aligned.m16n8k16.row.col.f32.f16.f16.f32 "
        "{%0,%1,%2,%3}, {%4,%5,%6,%7}, {%8,%9}, {%0,%1,%2,%3};"
        : "+f"(d[0]), "+f"(d[1]), "+f"(d[2]), "+f"(d[3])
        : "r"(a[0]), "r"(a[1]), "r"(a[2]), "r"(a[3]), "r"(b[0]), "r"(b[1]));
}

// A-smem column swizzle for tgemm
#define AIDX(k2, m) ((m) ^ (((((k2) >> 1)) & 7) << 2))

// ================= fp32 GEMM via f16x2 split on mma.sync.m16n8k16 =================
// 2 CTAs/SM forced (reg cap 128) so MMA of one CTA overlaps load/split of the other.
__global__ __launch_bounds__(256, 2) void tgemm_k(
    const float* __restrict__ A, const float* __restrict__ B,
    const float* __restrict__ bias, float* __restrict__ C,
    int M, int N, int K, float alpha,
    long long sA, long long sB, long long sC, int mode)
{
    __shared__ uint32_t As_hi[16][136];
    __shared__ uint32_t As_lo[16][136];
    __shared__ uint32_t Bs_hi[16][72];
    __shared__ uint32_t Bs_lo[16][72];

    const int tid  = threadIdx.x;
    const int lane = tid & 31;
    const int wid  = tid >> 5;
    const int wm = (wid >> 1) * 32;
    const int wn = (wid & 1) * 32;
    const int r0 = lane >> 2;
    const int c0 = lane & 3;

    const int rowBase = blockIdx.y * 128;
    const int colBase = blockIdx.x * 64;

    const float* Ag = A + blockIdx.z * sA;
    const float* Bg = B + blockIdx.z * sB;
    const long long zoff = blockIdx.z * sC;

    const int bn = tid & 63;
    const int bkg = tid >> 6;

    float acc[2][4][4];
    #pragma unroll
    for (int t = 0; t < 2; t++)
        #pragma unroll
        for (int u = 0; u < 4; u++)
            #pragma unroll
            for (int i = 0; i < 4; i++) acc[t][u][i] = 0.f;

    float4 av[4];
    float  bv[8];
    #pragma unroll
    for (int i = 0; i < 4; i++) {
        int f = tid + i * 256;
        int m = f >> 3, sl = f & 7;
        av[i] = *(const float4*)(Ag + (long long)(rowBase + m) * K + sl * 4);
    }
    #pragma unroll
    for (int j = 0; j < 8; j++)
        bv[j] = Bg[(long long)(bkg * 8 + j) * N + colBase + bn];

    const int nchunk = K / 32;
    for (int c = 0; c < nchunk; c++) {
        #pragma unroll
        for (int i = 0; i < 4; i++) {
            int f = tid + i * 256;
            int m = f >> 3, sl = f & 7;
            int k2a = sl * 2, k2b = sl * 2 + 1;
            uint32_t lo, hi;
            hi = pack_split(av[i].x, av[i].y, lo);
            As_hi[k2a][AIDX(k2a, m)] = hi;  As_lo[k2a][AIDX(k2a, m)] = lo;
            hi = pack_split(av[i].z, av[i].w, lo);
            As_hi[k2b][AIDX(k2b, m)] = hi;  As_lo[k2b][AIDX(k2b, m)] = lo;
        }
        #pragma unroll
        for (int j2 = 0; j2 < 4; j2++) {
            uint32_t lo, hi;
            hi = pack_split(bv[j2 * 2], bv[j2 * 2 + 1], lo);
            Bs_hi[bkg * 4 + j2][bn] = hi;
            Bs_lo[bkg * 4 + j2][bn] = lo;
        }
        __syncthreads();

        if (c + 1 < nchunk) {
            int k0 = (c + 1) * 32;
            #pragma unroll
            for (int i = 0; i < 4; i++) {
                int f = tid + i * 256;
                int m = f >> 3, sl = f & 7;
                av[i] = *(const float4*)(Ag + (long long)(rowBase + m) * K + k0 + sl * 4);
            }
            #pragma unroll
            for (int j = 0; j < 8; j++)
                bv[j] = Bg[(long long)(k0 + bkg * 8 + j) * N + colBase + bn];
        }

        #pragma unroll
        for (int ks = 0; ks < 2; ks++) {
            const int kb = ks * 8;
            uint32_t ahi[2][4], alo[2][4], bhi[4][2], blo[4][2];
            #pragma unroll
            for (int t = 0; t < 2; t++) {
                int mb = wm + t * 16 + r0;
                int ka = kb + c0, kc = kb + c0 + 4;
                ahi[t][0] = As_hi[ka][AIDX(ka, mb)];
                ahi[t][1] = As_hi[ka][AIDX(ka, mb + 8)];
                ahi[t][2] = As_hi[kc][AIDX(kc, mb)];
                ahi[t][3] = As_hi[kc][AIDX(kc, mb + 8)];
                alo[t][0] = As_lo[ka][AIDX(ka, mb)];
                alo[t][1] = As_lo[ka][AIDX(ka, mb + 8)];
                alo[t][2] = As_lo[kc][AIDX(kc, mb)];
                alo[t][3] = As_lo[kc][AIDX(kc, mb + 8)];
            }
            #pragma unroll
            for (int u = 0; u < 4; u++) {
                int nb = wn + u * 8 + r0;
                bhi[u][0] = Bs_hi[kb + c0][nb];
                bhi[u][1] = Bs_hi[kb + c0 + 4][nb];
                blo[u][0] = Bs_lo[kb + c0][nb];
                blo[u][1] = Bs_lo[kb + c0 + 4][nb];
            }
            #pragma unroll
            for (int t = 0; t < 2; t++)
                #pragma unroll
                for (int u = 0; u < 4; u++) {
                    mma_f16(acc[t][u], alo[t], bhi[u]);
                    mma_f16(acc[t][u], ahi[t], blo[u]);
                    mma_f16(acc[t][u], ahi[t], bhi[u]);
                }
        }
        __syncthreads();
    }

    #pragma unroll
    for (int t = 0; t < 2; t++) {
        int row0 = rowBase + wm + t * 16 + r0;
        #pragma unroll
        for (int u = 0; u < 4; u++) {
            int col0 = colBase + wn + u * 8 + c0 * 2;
            #pragma unroll
            for (int i = 0; i < 4; i++) {
                int r = row0 + (i >> 1) * 8;
                int c = col0 + (i & 1);
                float v = acc[t][u][i] * alpha;
                if (bias) v += bias[c];
                long long idx;
                if (mode == 0) {
                    idx = zoff + (long long)r * N + c;
                } else {
                    int b = r >> 9, n = r & 511, h = c >> 6, d = c & 63;
                    if (mode == 1) idx = ((long long)(b * H + h) * NN + n) * DK + d;
                    else           idx = ((long long)(b * H + h) * DK + d) * NN + n;
                }
                C[idx] = v;
            }
        }
    }
}

// ---------------- Wrk transpose: WrkT[d][e] = Wrk[e][d] ----------------
__global__ void transp_wrk(const float* __restrict__ Wrk)
{
    int i = blockIdx.x * 256 + threadIdx.x;
    if (i < DR * DK) {
        int e = i >> 6, d = i & 63;
        g_WrkT[d * DR + e] = Wrk[i];
    }
}

// ================= fused attention per (b,m), tensor-core phases =================
#define AT_A   8192
#define AT_AL  (AT_A + 4112)
#define AT_B   16416
#define AT_BL  (AT_B + 4352)
#define ATTN_SMEM (25120 * 4)

__global__ __launch_bounds__(256, 2) void attn_k(
    const float* __restrict__ rk, const float* __restrict__ rv)
{
    extern __shared__ uint32_t sm[];
    float*    s_score = (float*)sm;
    uint32_t* qa_hi = sm + AT_A;    // [16][65]
    uint32_t* qa_lo = sm + AT_AL;
    uint32_t* sA_hi = sm + AT_A;    // [16][257] (phase 3, reuses region)
    uint32_t* sA_lo = sm + AT_A + 4112;
    uint32_t* sb_hi = sm + AT_B;
    uint32_t* sb_lo = sm + AT_BL;

    const int tid  = threadIdx.x;
    const int lane = tid & 31;
    const int w    = tid >> 5;
    const int g    = lane >> 2;      // 0..7
    const int tig  = lane & 3;       // 0..3

    const int m = blockIdx.x, b = blockIdx.y;

    // ---- load score rows (float4) ----
    {
        const float4* gs = (const float4*)g_score;
        float4* ss = (float4*)s_score;
        #pragma unroll
        for (int i = 0; i < 8; i++) {
            int f = tid + i * 256;             // 0..2047
            int h = f >> 7, c4 = f & 127;
            ss[h * 128 + c4] = gs[(((long long)(b * H + h) * NN + m) * NN >> 2) + c4];
        }
    }
    // ---- load + split q~ [16][128] into qa (k-pairs) ----
    #pragma unroll
    for (int i = 0; i < 4; i++) {
        int f = tid + i * 256;                 // 0..1023 pairs
        int h = f >> 6, p = f & 63;
        const float* qp = g_qtil + ((long long)(b * H + h) * NN + m) * DR + p * 2;
        uint32_t lo, hi = pack_split(qp[0], qp[1], lo);
        qa_hi[h * 65 + p] = hi;
        qa_lo[h * 65 + p] = lo;
    }
    __syncthreads();

    // ---- phase 1: score[h][n] += q~[h,:] . r_k[b,m,n,:]  (mma, chunks of 64 n) ----
    const float* rkb0 = rk + ((long long)(b * NN + m)) * NN * DR;
    for (int nc = 0; nc < 8; nc++) {
        const float* rkb = rkb0 + (long long)nc * 64 * DR;
        #pragma unroll
        for (int i = 0; i < 8; i++) {
            int f = tid + i * 256;             // 0..2047 float4
            int nl = f >> 5, c4 = f & 31;
            float4 v = *(const float4*)(rkb + nl * DR + c4 * 4);
            uint32_t lo, hi;
            hi = pack_split(v.x, v.y, lo);
            sb_hi[nl * 68 + c4 * 2] = hi;  sb_lo[nl * 68 + c4 * 2] = lo;
            hi = pack_split(v.z, v.w, lo);
            sb_hi[nl * 68 + c4 * 2 + 1] = hi;  sb_lo[nl * 68 + c4 * 2 + 1] = lo;
        }
        __syncthreads();

        float acc[4] = {0.f, 0.f, 0.f, 0.f};
        #pragma unroll
        for (int ks = 0; ks < 8; ks++) {
            int k2 = ks * 8 + tig;
            uint32_t ah[4], al[4], bh[2], bl[2];
            ah[0] = qa_hi[g * 65 + k2];        al[0] = qa_lo[g * 65 + k2];
            ah[1] = qa_hi[(g + 8) * 65 + k2];  al[1] = qa_lo[(g + 8) * 65 + k2];
            ah[2] = qa_hi[g * 65 + k2 + 4];    al[2] = qa_lo[g * 65 + k2 + 4];
            ah[3] = qa_hi[(g + 8) * 65 + k2 + 4]; al[3] = qa_lo[(g + 8) * 65 + k2 + 4];
            int nrow = w * 8 + g;
            bh[0] = sb_hi[nrow * 68 + k2];     bl[0] = sb_lo[nrow * 68 + k2];
            bh[1] = sb_hi[nrow * 68 + k2 + 4]; bl[1] = sb_lo[nrow * 68 + k2 + 4];
            mma_f16(acc, al, bh);
            mma_f16(acc, ah, bl);
            mma_f16(acc, ah, bh);
        }
        int col = nc * 64 + w * 8 + tig * 2;
        s_score[g * NN + col]           += acc[0];
        s_score[g * NN + col + 1]       += acc[1];
        s_score[(g + 8) * NN + col]     += acc[2];
        s_score[(g + 8) * NN + col + 1] += acc[3];
        __syncthreads();
    }

    // ---- phase 2: softmax per head row; write att to gmem for av GEMM ----
    for (int h = w * 2; h < w * 2 + 2; h++) {
        float* row = s_score + h * NN;
        float mx = -1e30f;
        for (int n = lane; n < NN; n += 32) mx = fmaxf(mx, row[n]);
        #pragma unroll
        for (int o = 16; o; o >>= 1) mx = fmaxf(mx, __shfl_xor_sync(0xffffffffu, mx, o));
        float sum = 0.f;
        for (int n = lane; n < NN; n += 32) {
            float e = __expf(row[n] - mx);
            row[n] = e;
            sum += e;
        }
        #pragma unroll
        for (int o = 16; o; o >>= 1) sum += __shfl_xor_sync(0xffffffffu, sum, o);
        float inv = 1.0f / sum;
        float* gatt = g_score + ((long long)(b * H + h) * NN + m) * NN;
        for (int n = lane; n < NN; n += 32) {
            float a = row[n] * inv;
            row[n] = a;
            gatt[n] = a;
        }
    }
    __syncthreads();

    // ---- phase 2.5: split att into sA (k-pairs over n) ----
    #pragma unroll
    for (int i = 0; i < 16; i++) {
        int f = tid + i * 256;                 // 0..4095
        int h = f >> 8, k2 = f & 255;
        uint32_t lo, hi = pack_split(s_score[h * NN + k2 * 2], s_score[h * NN + k2 * 2 + 1], lo);
        sA_hi[h * 257 + k2] = hi;
        sA_lo[h * 257 + k2] = lo;
    }
    __syncthreads();

    // ---- phase 3: u[h][e] = att[h][:] @ r_v[b,m,:,e]  (mma, chunks of 64 n) ----
    float uacc[2][4];
    #pragma unroll
    for (int t = 0; t < 2; t++)
        #pragma unroll
        for (int i = 0; i < 4; i++) uacc[t][i] = 0.f;

    const float* rvb0 = rv + ((long long)(b * NN + m)) * NN * DR;
    for (int nc = 0; nc < 8; nc++) {
        const float* rvb = rvb0 + (long long)nc * 64 * DR;
        #pragma unroll
        for (int i = 0; i < 16; i++) {
            int f = tid + i * 256;             // 0..4095
            int e = f & 127, n2 = f >> 7;
            float x = rvb[(2 * n2) * DR + e];
            float y = rvb[(2 * n2 + 1) * DR + e];
            uint32_t lo, hi = pack_split(x, y, lo);
            sb_hi[e * 33 + n2] = hi;
            sb_lo[e * 33 + n2] = lo;
        }
        __syncthreads();

        #pragma unroll
        for (int t = 0; t < 2; t++) {
            int ecol = (w * 2 + t) * 8 + g;
            #pragma unroll
            for (int ks = 0; ks < 4; ks++) {
                int k2g = nc * 32 + ks * 8 + tig;
                int k2l = ks * 8 + tig;
                uint32_t ah[4], al[4], bh[2], bl[2];
                ah[0] = sA_hi[g * 257 + k2g];        al[0] = sA_lo[g * 257 + k2g];
                ah[1] = sA_hi[(g + 8) * 257 + k2g];  al[1] = sA_lo[(g + 8) * 257 + k2g];
                ah[2] = sA_hi[g * 257 + k2g + 4];    al[2] = sA_lo[g * 257 + k2g + 4];
                ah[3] = sA_hi[(g + 8) * 257 + k2g + 4]; al[3] = sA_lo[(g + 8) * 257 + k2g + 4];
                bh[0] = sb_hi[ecol * 33 + k2l];      bl[0] = sb_lo[ecol * 33 + k2l];
                bh[1] = sb_hi[ecol * 33 + k2l + 4];  bl[1] = sb_lo[ecol * 33 + k2l + 4];
                mma_f16(uacc[t], al, bh);
                mma_f16(uacc[t], ah, bl);
                mma_f16(uacc[t], ah, bh);
            }
        }
        __syncthreads();
    }

    // ---- write u ----
    #pragma unroll
    for (int t = 0; t < 2; t++) {
        int e0 = (w * 2 + t) * 8 + tig * 2;
        float* u0 = g_u + ((long long)(b * H + g) * NN + m) * DR;
        float* u8 = g_u + ((long long)(b * H + g + 8) * NN + m) * DR;
        u0[e0]     = uacc[t][0];
        u0[e0 + 1] = uacc[t][1];
        u8[e0]     = uacc[t][2];
        u8[e0 + 1] = uacc[t][3];
    }
}

// ---------------- val assembly: val[b,m,h*64+d] = av + u@Wrv + brv ----------------
__global__ __launch_bounds__(256) void assemble_k(
    const float* __restrict__ Wrv, const float* __restrict__ brv)
{
    __shared__ float sW[DR * DK];   // 32 KB
    __shared__ float su[H * DR];    // 8 KB
    int tid = threadIdx.x;
    int m = blockIdx.x, b = blockIdx.y;

    for (int i = tid; i < DR * DK; i += 256) sW[i] = Wrv[i];
    for (int i = tid; i < H * DR; i += 256) {
        int h = i >> 7, e = i & 127;
        su[i] = g_u[((long long)(b * H + h) * NN + m) * DR + e];
    }
    __syncthreads();

    for (int c = tid; c < DD; c += 256) {
        int h = c >> 6, d = c & 63;
        float acc = brv[d] + g_av[((long long)(b * H + h) * NN + m) * DK + d];
        const float* uu = su + h * DR;
        #pragma unroll 8
        for (int e = 0; e < DR; e++) acc += uu[e] * sW[e * DK + d];
        g_val[((long long)(b * NN + m)) * DD + c] = acc;
    }
}

// ---------------- host launcher ----------------
extern "C" void kernel_launch(void* const* d_in, const int* in_sizes, int n_in,
                              void* d_out, int out_size)
{
    const float* q   = (const float*)d_in[0];
    const float* k   = (const float*)d_in[1];
    const float* v   = (const float*)d_in[2];
    const float* r_k = (const float*)d_in[3];
    const float* r_v = (const float*)d_in[4];
    const float* Wq  = (const float*)d_in[5];
    const float* bq  = (const float*)d_in[6];
    const float* Wk  = (const float*)d_in[7];
    const float* bk  = (const float*)d_in[8];
    const float* Wv  = (const float*)d_in[9];
    const float* bv  = (const float*)d_in[10];
    const float* Wrk = (const float*)d_in[11];
    // d_in[12] = brk: per-row-constant in softmax -> drops out, unused
    const float* Wrv = (const float*)d_in[13];
    const float* brv = (const float*)d_in[14];
    const float* Wo  = (const float*)d_in[15];
    const float* bo  = (const float*)d_in[16];
    float* out = (float*)d_out;

    float *qh, *khT, *vh, *qtil, *score, *av, *val, *WrkT;
    cudaGetSymbolAddress((void**)&qh,    g_qh);
    cudaGetSymbolAddress((void**)&khT,   g_khT);
    cudaGetSymbolAddress((void**)&vh,    g_vh);
    cudaGetSymbolAddress((void**)&qtil,  g_qtil);
    cudaGetSymbolAddress((void**)&score, g_score);
    cudaGetSymbolAddress((void**)&av,    g_av);
    cudaGetSymbolAddress((void**)&val,   g_val);
    cudaGetSymbolAddress((void**)&WrkT,  g_WrkT);

    cudaFuncSetAttribute(attn_k, cudaFuncAttributeMaxDynamicSharedMemorySize, ATTN_SMEM);

    dim3 blk(256);
    const float scale = 0.125f;  // 1/sqrt(64)

    // launch #1: tiny transpose (keeps ncu -s 5 on an interesting kernel)
    transp_wrk<<<32, 256>>>(Wrk);

    // projections: qh (HEAD), khT (HEADT), vh (HEAD).  M=2048,N=1024,K=1024
    tgemm_k<<<dim3(16, 16, 1), blk>>>(q, Wq, bq, qh,  2048, 1024, 1024, 1.0f, 0, 0, 0, 1);
    tgemm_k<<<dim3(16, 16, 1), blk>>>(k, Wk, bk, khT, 2048, 1024, 1024, 1.0f, 0, 0, 0, 2);
    tgemm_k<<<dim3(16, 16, 1), blk>>>(v, Wv, bv, vh,  2048, 1024, 1024, 1.0f, 0, 0, 0, 1);

    // q~ = qh @ Wrk^T   M=32768, N=128, K=64
    tgemm_k<<<dim3(2, 256, 1), blk>>>(qh, WrkT, nullptr, qtil,
                                      BH * NN, DR, DK, 1.0f, 0, 0, 0, 0);

    // scoreQK[bh] = scale * qh[bh] @ khT[bh]   M=512,N=512,K=64, 64 batches
    tgemm_k<<<dim3(8, 4, BH), blk>>>(qh, khT, nullptr, score,
                                     NN, NN, DK, scale,
                                     (long long)NN * DK, (long long)DK * NN,
                                     (long long)NN * NN, 0);

    // fused bias + softmax + u (tensor-core phases)
    attn_k<<<dim3(NN, BB, 1), blk, ATTN_SMEM>>>(r_k, r_v);

    // av[bh] = att[bh] @ vh[bh]   M=512,N=64,K=512, 64 batches
    tgemm_k<<<dim3(1, 4, BH), blk>>>(score, vh, nullptr, av,
                                     NN, DK, NN, 1.0f,
                                     (long long)NN * NN, (long long)NN * DK,
                                     (long long)NN * DK, 0);

    // val = av + u @ Wrv + brv   (written in [B,N,D] layout)
    assemble_k<<<dim3(NN, BB, 1), blk>>>(Wrv, brv);

    // out = val @ Wo + bo   M=2048,N=1024,K=1024
    tgemm_k<<<dim3(16, 16, 1), blk>>>(val, Wo, bo, out, 2048, 1024, 1024, 1.0f, 0, 0, 0, 0);
}

// round 10
// speedup vs baseline: 1.1845x; 1.1845x over previous
#include <cuda_runtime.h>
#include <cuda_fp16.h>
#include <math.h>
#include <stdint.h>

#define H   16
#define BB  4
#define NN  512
#define DD  1024
#define DK  64
#define DR  128
#define BH  (BB*H)   // 64

// ---------------- scratch (static device globals; no allocation) ----------------
__device__ float g_qh  [BH*NN*DK];        // [bh][n][d]     8 MB
__device__ float g_khT [BH*DK*NN];        // [bh][d][n]     8 MB
__device__ float g_vh  [BH*NN*DK];        // [bh][n][d]     8 MB
__device__ float g_qtil[BH*NN*DR];        // [bh][n][e]    16 MB
__device__ float g_score[BH*NN*NN];       // [bh][m][n]    64 MB (score -> att in place)
__device__ float g_u   [BH*NN*DR];        // [bh][m][e]    16 MB
__device__ float g_av  [BH*NN*DK];        // [bh][m][d]     8 MB
__device__ float g_val [BB*NN*DD];        // [b][m][h*64+d] 8 MB
__device__ float g_WrkT[DK*DR];           // [d][e]

// ---------------- f16x2 helpers (packed cvt) ----------------
__device__ __forceinline__ uint32_t pack_split(float x, float y, uint32_t& lo2) {
    __half2 h2 = __float22half2_rn(make_float2(x, y));
    float2 back = __half22float2(h2);
    __half2 l2 = __float22half2_rn(make_float2(x - back.x, y - back.y));
    lo2 = *(uint32_t*)&l2;
    return *(uint32_t*)&h2;
}
__device__ __forceinline__ uint32_t pack_half(float x, float y) {
    __half2 h2 = __float22half2_rn(make_float2(x, y));
    return *(uint32_t*)&h2;
}

__device__ __forceinline__ void mma_f16(float* d, const uint32_t* a, const uint32_t* b) {
    asm volatile(
        "mma.sync.aligned.m16n8k16.row.col.f32.f16.f16.f32 "
        "{%0,%1,%2,%3}, {%4,%5,%6,%7}, {%8,%9}, {%0,%1,%2,%3};"
        : "+f"(d[0]), "+f"(d[1]), "+f"(d[2]), "+f"(d[3])
        : "r"(a[0]), "r"(a[1]), "r"(a[2]), "r"(a[3]), "r"(b[0]), "r"(b[1]));
}

// A-smem column swizzle for tgemm
#define AIDX(k2, m) ((m) ^ (((((k2) >> 1)) & 7) << 2))

// ================= fp32 GEMM via f16x2 split on mma.sync.m16n8k16 =================
// (reverted to R6/R7 launch bounds — 160 regs, no spills; proven 74.5 us config)
__global__ __launch_bounds__(256) void tgemm_k(
    const float* __restrict__ A, const float* __restrict__ B,
    const float* __restrict__ bias, float* __restrict__ C,
    int M, int N, int K, float alpha,
    long long sA, long long sB, long long sC, int mode)
{
    __shared__ uint32_t As_hi[16][136];
    __shared__ uint32_t As_lo[16][136];
    __shared__ uint32_t Bs_hi[16][72];
    __shared__ uint32_t Bs_lo[16][72];

    const int tid  = threadIdx.x;
    const int lane = tid & 31;
    const int wid  = tid >> 5;
    const int wm = (wid >> 1) * 32;
    const int wn = (wid & 1) * 32;
    const int r0 = lane >> 2;
    const int c0 = lane & 3;

    const int rowBase = blockIdx.y * 128;
    const int colBase = blockIdx.x * 64;

    const float* Ag = A + blockIdx.z * sA;
    const float* Bg = B + blockIdx.z * sB;
    const long long zoff = blockIdx.z * sC;

    const int bn = tid & 63;
    const int bkg = tid >> 6;

    float acc[2][4][4];
    #pragma unroll
    for (int t = 0; t < 2; t++)
        #pragma unroll
        for (int u = 0; u < 4; u++)
            #pragma unroll
            for (int i = 0; i < 4; i++) acc[t][u][i] = 0.f;

    float4 av[4];
    float  bv[8];
    #pragma unroll
    for (int i = 0; i < 4; i++) {
        int f = tid + i * 256;
        int m = f >> 3, sl = f & 7;
        av[i] = *(const float4*)(Ag + (long long)(rowBase + m) * K + sl * 4);
    }
    #pragma unroll
    for (int j = 0; j < 8; j++)
        bv[j] = Bg[(long long)(bkg * 8 + j) * N + colBase + bn];

    const int nchunk = K / 32;
    for (int c = 0; c < nchunk; c++) {
        #pragma unroll
        for (int i = 0; i < 4; i++) {
            int f = tid + i * 256;
            int m = f >> 3, sl = f & 7;
            int k2a = sl * 2, k2b = sl * 2 + 1;
            uint32_t lo, hi;
            hi = pack_split(av[i].x, av[i].y, lo);
            As_hi[k2a][AIDX(k2a, m)] = hi;  As_lo[k2a][AIDX(k2a, m)] = lo;
            hi = pack_split(av[i].z, av[i].w, lo);
            As_hi[k2b][AIDX(k2b, m)] = hi;  As_lo[k2b][AIDX(k2b, m)] = lo;
        }
        #pragma unroll
        for (int j2 = 0; j2 < 4; j2++) {
            uint32_t lo, hi;
            hi = pack_split(bv[j2 * 2], bv[j2 * 2 + 1], lo);
            Bs_hi[bkg * 4 + j2][bn] = hi;
            Bs_lo[bkg * 4 + j2][bn] = lo;
        }
        __syncthreads();

        if (c + 1 < nchunk) {
            int k0 = (c + 1) * 32;
            #pragma unroll
            for (int i = 0; i < 4; i++) {
                int f = tid + i * 256;
                int m = f >> 3, sl = f & 7;
                av[i] = *(const float4*)(Ag + (long long)(rowBase + m) * K + k0 + sl * 4);
            }
            #pragma unroll
            for (int j = 0; j < 8; j++)
                bv[j] = Bg[(long long)(k0 + bkg * 8 + j) * N + colBase + bn];
        }

        #pragma unroll
        for (int ks = 0; ks < 2; ks++) {
            const int kb = ks * 8;
            uint32_t ahi[2][4], alo[2][4], bhi[4][2], blo[4][2];
            #pragma unroll
            for (int t = 0; t < 2; t++) {
                int mb = wm + t * 16 + r0;
                int ka = kb + c0, kc = kb + c0 + 4;
                ahi[t][0] = As_hi[ka][AIDX(ka, mb)];
                ahi[t][1] = As_hi[ka][AIDX(ka, mb + 8)];
                ahi[t][2] = As_hi[kc][AIDX(kc, mb)];
                ahi[t][3] = As_hi[kc][AIDX(kc, mb + 8)];
                alo[t][0] = As_lo[ka][AIDX(ka, mb)];
                alo[t][1] = As_lo[ka][AIDX(ka, mb + 8)];
                alo[t][2] = As_lo[kc][AIDX(kc, mb)];
                alo[t][3] = As_lo[kc][AIDX(kc, mb + 8)];
            }
            #pragma unroll
            for (int u = 0; u < 4; u++) {
                int nb = wn + u * 8 + r0;
                bhi[u][0] = Bs_hi[kb + c0][nb];
                bhi[u][1] = Bs_hi[kb + c0 + 4][nb];
                blo[u][0] = Bs_lo[kb + c0][nb];
                blo[u][1] = Bs_lo[kb + c0 + 4][nb];
            }
            #pragma unroll
            for (int t = 0; t < 2; t++)
                #pragma unroll
                for (int u = 0; u < 4; u++) {
                    mma_f16(acc[t][u], alo[t], bhi[u]);
                    mma_f16(acc[t][u], ahi[t], blo[u]);
                    mma_f16(acc[t][u], ahi[t], bhi[u]);
                }
        }
        __syncthreads();
    }

    #pragma unroll
    for (int t = 0; t < 2; t++) {
        int row0 = rowBase + wm + t * 16 + r0;
        #pragma unroll
        for (int u = 0; u < 4; u++) {
            int col0 = colBase + wn + u * 8 + c0 * 2;
            #pragma unroll
            for (int i = 0; i < 4; i++) {
                int r = row0 + (i >> 1) * 8;
                int c = col0 + (i & 1);
                float v = acc[t][u][i] * alpha;
                if (bias) v += bias[c];
                long long idx;
                if (mode == 0) {
                    idx = zoff + (long long)r * N + c;
                } else {
                    int b = r >> 9, n = r & 511, h = c >> 6, d = c & 63;
                    if (mode == 1) idx = ((long long)(b * H + h) * NN + n) * DK + d;
                    else           idx = ((long long)(b * H + h) * DK + d) * NN + n;
                }
                C[idx] = v;
            }
        }
    }
}

// ---------------- Wrk transpose: WrkT[d][e] = Wrk[e][d] ----------------
__global__ void transp_wrk(const float* __restrict__ Wrk)
{
    int i = blockIdx.x * 256 + threadIdx.x;
    if (i < DR * DK) {
        int e = i >> 6, d = i & 63;
        g_WrkT[d * DR + e] = Wrk[i];
    }
}

// ================= fused attention per (b,m), tensor-core phases =================
// r_k / r_v are single-half (linear terms; error ~2^-11 stays well under 1e-3).
// q~ and att keep hi+lo double-split.
// smem (u32 units):
//  [0, 8192)        s_score fp32 [16][512]
//  [8192, 16416)    A-region: phase1 qa_hi[16][65], qa_lo; phase3 sA_hi[16][257], sA_lo
//  [16416, 20768)   chunk B (hi only): phase1 [64][68]; phase3 [128][33]
#define AT_A   8192
#define AT_AL  (AT_A + 4112)
#define AT_B   16416
#define ATTN_SMEM (20768 * 4)

__global__ __launch_bounds__(256, 2) void attn_k(
    const float* __restrict__ rk, const float* __restrict__ rv)
{
    extern __shared__ uint32_t sm[];
    float*    s_score = (float*)sm;
    uint32_t* qa_hi = sm + AT_A;    // [16][65]
    uint32_t* qa_lo = sm + AT_AL;
    uint32_t* sA_hi = sm + AT_A;    // [16][257] (phase 3, reuses region)
    uint32_t* sA_lo = sm + AT_A + 4112;
    uint32_t* sb_hi = sm + AT_B;

    const int tid  = threadIdx.x;
    const int lane = tid & 31;
    const int w    = tid >> 5;
    const int g    = lane >> 2;      // 0..7
    const int tig  = lane & 3;       // 0..3

    const int m = blockIdx.x, b = blockIdx.y;

    // ---- load score rows (float4) ----
    {
        const float4* gs = (const float4*)g_score;
        float4* ss = (float4*)s_score;
        #pragma unroll
        for (int i = 0; i < 8; i++) {
            int f = tid + i * 256;             // 0..2047
            int h = f >> 7, c4 = f & 127;
            ss[h * 128 + c4] = gs[(((long long)(b * H + h) * NN + m) * NN >> 2) + c4];
        }
    }
    // ---- load + split q~ [16][128] into qa (k-pairs) ----
    #pragma unroll
    for (int i = 0; i < 4; i++) {
        int f = tid + i * 256;                 // 0..1023 pairs
        int h = f >> 6, p = f & 63;
        const float* qp = g_qtil + ((long long)(b * H + h) * NN + m) * DR + p * 2;
        uint32_t lo, hi = pack_split(qp[0], qp[1], lo);
        qa_hi[h * 65 + p] = hi;
        qa_lo[h * 65 + p] = lo;
    }
    __syncthreads();

    // ---- phase 1: score[h][n] += q~[h,:] . r_k[b,m,n,:]  (mma, chunks of 64 n) ----
    const float* rkb0 = rk + ((long long)(b * NN + m)) * NN * DR;
    for (int nc = 0; nc < 8; nc++) {
        const float* rkb = rkb0 + (long long)nc * 64 * DR;
        #pragma unroll
        for (int i = 0; i < 8; i++) {
            int f = tid + i * 256;             // 0..2047 float4
            int nl = f >> 5, c4 = f & 31;
            float4 v = *(const float4*)(rkb + nl * DR + c4 * 4);
            sb_hi[nl * 68 + c4 * 2]     = pack_half(v.x, v.y);
            sb_hi[nl * 68 + c4 * 2 + 1] = pack_half(v.z, v.w);
        }
        __syncthreads();

        float acc[4] = {0.f, 0.f, 0.f, 0.f};
        #pragma unroll
        for (int ks = 0; ks < 8; ks++) {
            int k2 = ks * 8 + tig;
            uint32_t ah[4], al[4], bh[2];
            ah[0] = qa_hi[g * 65 + k2];        al[0] = qa_lo[g * 65 + k2];
            ah[1] = qa_hi[(g + 8) * 65 + k2];  al[1] = qa_lo[(g + 8) * 65 + k2];
            ah[2] = qa_hi[g * 65 + k2 + 4];    al[2] = qa_lo[g * 65 + k2 + 4];
            ah[3] = qa_hi[(g + 8) * 65 + k2 + 4]; al[3] = qa_lo[(g + 8) * 65 + k2 + 4];
            int nrow = w * 8 + g;
            bh[0] = sb_hi[nrow * 68 + k2];
            bh[1] = sb_hi[nrow * 68 + k2 + 4];
            mma_f16(acc, al, bh);
            mma_f16(acc, ah, bh);
        }
        int col = nc * 64 + w * 8 + tig * 2;
        s_score[g * NN + col]           += acc[0];
        s_score[g * NN + col + 1]       += acc[1];
        s_score[(g + 8) * NN + col]     += acc[2];
        s_score[(g + 8) * NN + col + 1] += acc[3];
        __syncthreads();
    }

    // ---- phase 2: softmax per head row; write att to gmem for av GEMM ----
    for (int h = w * 2; h < w * 2 + 2; h++) {
        float* row = s_score + h * NN;
        float mx = -1e30f;
        for (int n = lane; n < NN; n += 32) mx = fmaxf(mx, row[n]);
        #pragma unroll
        for (int o = 16; o; o >>= 1) mx = fmaxf(mx, __shfl_xor_sync(0xffffffffu, mx, o));
        float sum = 0.f;
        for (int n = lane; n < NN; n += 32) {
            float e = __expf(row[n] - mx);
            row[n] = e;
            sum += e;
        }
        #pragma unroll
        for (int o = 16; o; o >>= 1) sum += __shfl_xor_sync(0xffffffffu, sum, o);
        float inv = 1.0f / sum;
        float* gatt = g_score + ((long long)(b * H + h) * NN + m) * NN;
        for (int n = lane; n < NN; n += 32) {
            float a = row[n] * inv;
            row[n] = a;
            gatt[n] = a;
        }
    }
    __syncthreads();

    // ---- phase 2.5: split att into sA (k-pairs over n) ----
    #pragma unroll
    for (int i = 0; i < 16; i++) {
        int f = tid + i * 256;                 // 0..4095
        int h = f >> 8, k2 = f & 255;
        uint32_t lo, hi = pack_split(s_score[h * NN + k2 * 2], s_score[h * NN + k2 * 2 + 1], lo);
        sA_hi[h * 257 + k2] = hi;
        sA_lo[h * 257 + k2] = lo;
    }
    __syncthreads();

    // ---- phase 3: u[h][e] = att[h][:] @ r_v[b,m,:,e]  (mma, chunks of 64 n) ----
    float uacc[2][4];
    #pragma unroll
    for (int t = 0; t < 2; t++)
        #pragma unroll
        for (int i = 0; i < 4; i++) uacc[t][i] = 0.f;

    const float* rvb0 = rv + ((long long)(b * NN + m)) * NN * DR;
    for (int nc = 0; nc < 8; nc++) {
        const float* rvb = rvb0 + (long long)nc * 64 * DR;
        #pragma unroll
        for (int i = 0; i < 16; i++) {
            int f = tid + i * 256;             // 0..4095
            int e = f & 127, n2 = f >> 7;
            float x = rvb[(2 * n2) * DR + e];
            float y = rvb[(2 * n2 + 1) * DR + e];
            sb_hi[e * 33 + n2] = pack_half(x, y);
        }
        __syncthreads();

        #pragma unroll
        for (int t = 0; t < 2; t++) {
            int ecol = (w * 2 + t) * 8 + g;
            #pragma unroll
            for (int ks = 0; ks < 4; ks++) {
                int k2g = nc * 32 + ks * 8 + tig;
                int k2l = ks * 8 + tig;
                uint32_t ah[4], al[4], bh[2];
                ah[0] = sA_hi[g * 257 + k2g];        al[0] = sA_lo[g * 257 + k2g];
                ah[1] = sA_hi[(g + 8) * 257 + k2g];  al[1] = sA_lo[(g + 8) * 257 + k2g];
                ah[2] = sA_hi[g * 257 + k2g + 4];    al[2] = sA_lo[g * 257 + k2g + 4];
                ah[3] = sA_hi[(g + 8) * 257 + k2g + 4]; al[3] = sA_lo[(g + 8) * 257 + k2g + 4];
                bh[0] = sb_hi[ecol * 33 + k2l];
                bh[1] = sb_hi[ecol * 33 + k2l + 4];
                mma_f16(uacc[t], al, bh);
                mma_f16(uacc[t], ah, bh);
            }
        }
        __syncthreads();
    }

    // ---- write u ----
    #pragma unroll
    for (int t = 0; t < 2; t++) {
        int e0 = (w * 2 + t) * 8 + tig * 2;
        float* u0 = g_u + ((long long)(b * H + g) * NN + m) * DR;
        float* u8 = g_u + ((long long)(b * H + g + 8) * NN + m) * DR;
        u0[e0]     = uacc[t][0];
        u0[e0 + 1] = uacc[t][1];
        u8[e0]     = uacc[t][2];
        u8[e0 + 1] = uacc[t][3];
    }
}

// ---------------- val assembly: val[b,m,h*64+d] = av + u@Wrv + brv ----------------
__global__ __launch_bounds__(256) void assemble_k(
    const float* __restrict__ Wrv, const float* __restrict__ brv)
{
    __shared__ float sW[DR * DK];   // 32 KB
    __shared__ float su[H * DR];    // 8 KB
    int tid = threadIdx.x;
    int m = blockIdx.x, b = blockIdx.y;

    for (int i = tid; i < DR * DK; i += 256) sW[i] = Wrv[i];
    for (int i = tid; i < H * DR; i += 256) {
        int h = i >> 7, e = i & 127;
        su[i] = g_u[((long long)(b * H + h) * NN + m) * DR + e];
    }
    __syncthreads();

    for (int c = tid; c < DD; c += 256) {
        int h = c >> 6, d = c & 63;
        float acc = brv[d] + g_av[((long long)(b * H + h) * NN + m) * DK + d];
        const float* uu = su + h * DR;
        #pragma unroll 8
        for (int e = 0; e < DR; e++) acc += uu[e] * sW[e * DK + d];
        g_val[((long long)(b * NN + m)) * DD + c] = acc;
    }
}

// ---------------- host launcher ----------------
extern "C" void kernel_launch(void* const* d_in, const int* in_sizes, int n_in,
                              void* d_out, int out_size)
{
    const float* q   = (const float*)d_in[0];
    const float* k   = (const float*)d_in[1];
    const float* v   = (const float*)d_in[2];
    const float* r_k = (const float*)d_in[3];
    const float* r_v = (const float*)d_in[4];
    const float* Wq  = (const float*)d_in[5];
    const float* bq  = (const float*)d_in[6];
    const float* Wk  = (const float*)d_in[7];
    const float* bk  = (const float*)d_in[8];
    const float* Wv  = (const float*)d_in[9];
    const float* bv  = (const float*)d_in[10];
    const float* Wrk = (const float*)d_in[11];
    // d_in[12] = brk: per-row-constant in softmax -> drops out, unused
    const float* Wrv = (const float*)d_in[13];
    const float* brv = (const float*)d_in[14];
    const float* Wo  = (const float*)d_in[15];
    const float* bo  = (const float*)d_in[16];
    float* out = (float*)d_out;

    float *qh, *khT, *vh, *qtil, *score, *av, *val, *WrkT;
    cudaGetSymbolAddress((void**)&qh,    g_qh);
    cudaGetSymbolAddress((void**)&khT,   g_khT);
    cudaGetSymbolAddress((void**)&vh,    g_vh);
    cudaGetSymbolAddress((void**)&qtil,  g_qtil);
    cudaGetSymbolAddress((void**)&score, g_score);
    cudaGetSymbolAddress((void**)&av,    g_av);
    cudaGetSymbolAddress((void**)&val,   g_val);
    cudaGetSymbolAddress((void**)&WrkT,  g_WrkT);

    cudaFuncSetAttribute(attn_k, cudaFuncAttributeMaxDynamicSharedMemorySize, ATTN_SMEM);

    dim3 blk(256);
    const float scale = 0.125f;  // 1/sqrt(64)

    // launch #1: tiny transpose (keeps ncu -s 5 on an interesting kernel)
    transp_wrk<<<32, 256>>>(Wrk);

    // projections: qh (HEAD), khT (HEADT), vh (HEAD).  M=2048,N=1024,K=1024
    tgemm_k<<<dim3(16, 16, 1), blk>>>(q, Wq, bq, qh,  2048, 1024, 1024, 1.0f, 0, 0, 0, 1);
    tgemm_k<<<dim3(16, 16, 1), blk>>>(k, Wk, bk, khT, 2048, 1024, 1024, 1.0f, 0, 0, 0, 2);
    tgemm_k<<<dim3(16, 16, 1), blk>>>(v, Wv, bv, vh,  2048, 1024, 1024, 1.0f, 0, 0, 0, 1);

    // q~ = qh @ Wrk^T   M=32768, N=128, K=64
    tgemm_k<<<dim3(2, 256, 1), blk>>>(qh, WrkT, nullptr, qtil,
                                      BH * NN, DR, DK, 1.0f, 0, 0, 0, 0);

    // scoreQK[bh] = scale * qh[bh] @ khT[bh]   M=512,N=512,K=64, 64 batches
    tgemm_k<<<dim3(8, 4, BH), blk>>>(qh, khT, nullptr, score,
                                     NN, NN, DK, scale,
                                     (long long)NN * DK, (long long)DK * NN,
                                     (long long)NN * NN, 0);

    // fused bias + softmax + u (tensor-core phases; r_k/r_v single-half)
    attn_k<<<dim3(NN, BB, 1), blk, ATTN_SMEM>>>(r_k, r_v);

    // av[bh] = att[bh] @ vh[bh]   M=512,N=64,K=512, 64 batches
    tgemm_k<<<dim3(1, 4, BH), blk>>>(score, vh, nullptr, av,
                                     NN, DK, NN, 1.0f,
                                     (long long)NN * NN, (long long)NN * DK,
                                     (long long)NN * DK, 0);

    // val = av + u @ Wrv + brv   (written in [B,N,D] layout)
    assemble_k<<<dim3(NN, BB, 1), blk>>>(Wrv, brv);

    // out = val @ Wo + bo   M=2048,N=1024,K=1024
    tgemm_k<<<dim3(16, 16, 1), blk>>>(val, Wo, bo, out, 2048, 1024, 1024, 1.0f, 0, 0, 0, 0);
}